// round 9
// baseline (speedup 1.0000x reference)
#include <cuda_runtime.h>
#include <math.h>

#define F    1024
#define NJ   64
#define C    256
#define HID  1024
#define H    8
#define D    128
#define PARTS 2
#define FP   (F / PARTS)   // 512

#define XS_LD 20   // padded ld for x chunk

// Scratch (allocation-free rule: __device__ globals). 67 MB total.
__device__ float g_KVp[(size_t)PARTS * NJ * H * D * D];  // [p][(n*H+h)][m][d]
__device__ float g_Ksp[(size_t)PARTS * NJ * H * D];      // [p][(n*H+h)][d]

extern __shared__ float smem[];

__device__ __forceinline__ float elu1(float v) {
    return (v >= 0.f) ? (v + 1.f) : __expf(v);
}

// Packed dual fp32 FMA: d = a*b + d elementwise on (x,y) lanes.
__device__ __forceinline__ void fma2(float2& d, const float2 a, const float2 b) {
    asm("fma.rn.f32x2 %0, %1, %2, %0;"
        : "+l"(reinterpret_cast<unsigned long long&>(d))
        : "l"(reinterpret_cast<const unsigned long long&>(a)),
          "l"(reinterpret_cast<const unsigned long long&>(b)));
}

__device__ __forceinline__ float2 dup2(float v) { return make_float2(v, v); }

// ---------------------------------------------------------------------------
// Kernel A: per (n,h,p): fused K/V projection + partial KV outer product.
//   KVp[m][d] = sum_{f in part} V[f][m] * K[f][d],  Kps[d] = sum K[f][d]
// 256 threads, 8x8 microtile via packed f32x2 (acc pairs along columns).
// ---------------------------------------------------------------------------
__global__ __launch_bounds__(256) void kv_fused(
    const float* __restrict__ x,
    const float* __restrict__ Wk, const float* __restrict__ bk,
    const float* __restrict__ Wv, const float* __restrict__ bv)
{
    const int n = blockIdx.x;
    const int h = blockIdx.y;
    const int p = blockIdx.z;
    const int t  = threadIdx.x;
    const int tx = t & 15;
    const int ty = t >> 4;

    float* xs = smem;                  // [128][XS_LD]
    float* Ws = xs + 128 * XS_LD;      // [16][128]
    float* Ks = Ws + 16 * 128;         // [128][128]  K tile [f][d]
    float* Vs = Ks + 128 * 128;        // [128][128]  V tile [f][m]

    float2 kvacc[8][4];
    #pragma unroll
    for (int i = 0; i < 8; i++)
        #pragma unroll
        for (int j = 0; j < 4; j++) kvacc[i][j] = make_float2(0.f, 0.f);
    float ksum = 0.f;

    for (int f0 = p * FP; f0 < p * FP + FP; f0 += 128) {
        // ---- Phase 1: project K tile then V tile into smem ----
        #pragma unroll 1
        for (int mtx = 0; mtx < 2; mtx++) {
            const float* __restrict__ W    = mtx ? Wv : Wk;
            const float* __restrict__ bias = mtx ? bv : bk;
            float* __restrict__ Out        = mtx ? Vs : Ks;

            float2 acc[8][4];
            #pragma unroll
            for (int i = 0; i < 8; i++)
                #pragma unroll
                for (int j = 0; j < 4; j++) acc[i][j] = make_float2(0.f, 0.f);

            for (int c0 = 0; c0 < C; c0 += 16) {
                __syncthreads();
                #pragma unroll
                for (int it = 0; it < 2; it++) {
                    int idx = t + it * 256;
                    int row = idx >> 2, c4 = idx & 3;
                    float4 v = *(const float4*)
                        &x[((size_t)(f0 + row) * NJ + n) * C + c0 + c4 * 4];
                    *(float4*)&xs[row * XS_LD + c4 * 4] = v;
                }
                #pragma unroll
                for (int it = 0; it < 2; it++) {
                    int idx = t + it * 256;
                    int row = idx >> 5, c4 = idx & 31;
                    *(float4*)&Ws[row * 128 + c4 * 4] =
                        *(const float4*)&W[(size_t)(c0 + row) * HID + h * D + c4 * 4];
                }
                __syncthreads();

                #pragma unroll
                for (int kk = 0; kk < 16; kk++) {
                    float av[8];
                    #pragma unroll
                    for (int i = 0; i < 8; i++)
                        av[i] = xs[(ty * 8 + i) * XS_LD + kk];
                    float4 w0 = *(float4*)&Ws[kk * 128 + tx * 8];
                    float4 w1 = *(float4*)&Ws[kk * 128 + tx * 8 + 4];
                    float2 b2[4] = { make_float2(w0.x, w0.y), make_float2(w0.z, w0.w),
                                     make_float2(w1.x, w1.y), make_float2(w1.z, w1.w) };
                    #pragma unroll
                    for (int i = 0; i < 8; i++) {
                        float2 ad = dup2(av[i]);
                        #pragma unroll
                        for (int j = 0; j < 4; j++) fma2(acc[i][j], ad, b2[j]);
                    }
                }
            }
            // Epilogue: bias (+ feature map for K), store tile row-major
            #pragma unroll
            for (int i = 0; i < 8; i++) {
                float vals[8] = { acc[i][0].x, acc[i][0].y, acc[i][1].x, acc[i][1].y,
                                  acc[i][2].x, acc[i][2].y, acc[i][3].x, acc[i][3].y };
                float4 o[2];
                float* of = (float*)o;
                #pragma unroll
                for (int j = 0; j < 8; j++) {
                    float v = vals[j] + bias[h * D + tx * 8 + j];
                    of[j] = (mtx == 0) ? elu1(v) : v;
                }
                *(float4*)&Out[(ty * 8 + i) * 128 + tx * 8 + 0] = o[0];
                *(float4*)&Out[(ty * 8 + i) * 128 + tx * 8 + 4] = o[1];
            }
        }
        __syncthreads();

        if (t < 128) {
            #pragma unroll 8
            for (int ff = 0; ff < 128; ff++) ksum += Ks[ff * 128 + t];
        }

        // ---- Phase 2: KVp[m][d] += V[f][m] * K[f][d] ----
        #pragma unroll 4
        for (int ff = 0; ff < 128; ff++) {
            float4 a0 = *(float4*)&Vs[ff * 128 + ty * 8];
            float4 a1 = *(float4*)&Vs[ff * 128 + ty * 8 + 4];
            float4 k0 = *(float4*)&Ks[ff * 128 + tx * 8];
            float4 k1 = *(float4*)&Ks[ff * 128 + tx * 8 + 4];
            float av[8] = { a0.x, a0.y, a0.z, a0.w, a1.x, a1.y, a1.z, a1.w };
            float2 b2[4] = { make_float2(k0.x, k0.y), make_float2(k0.z, k0.w),
                             make_float2(k1.x, k1.y), make_float2(k1.z, k1.w) };
            #pragma unroll
            for (int i = 0; i < 8; i++) {
                float2 ad = dup2(av[i]);
                #pragma unroll
                for (int j = 0; j < 4; j++) fma2(kvacc[i][j], ad, b2[j]);
            }
        }
        __syncthreads();
    }

    const int nh = n * H + h;
    const size_t base = ((size_t)(p * NJ * H) + nh) * D * D;
    #pragma unroll
    for (int i = 0; i < 8; i++) {
        float4 v0 = make_float4(kvacc[i][0].x, kvacc[i][0].y, kvacc[i][1].x, kvacc[i][1].y);
        float4 v1 = make_float4(kvacc[i][2].x, kvacc[i][2].y, kvacc[i][3].x, kvacc[i][3].y);
        *(float4*)&g_KVp[base + (ty * 8 + i) * D + tx * 8 + 0] = v0;
        *(float4*)&g_KVp[base + (ty * 8 + i) * D + tx * 8 + 4] = v1;
    }
    if (t < 128) g_Ksp[((size_t)p * NJ * H + nh) * D + t] = ksum;
}

// ---------------------------------------------------------------------------
// Kernel B: per (l-tile, n, h): fused Q projection + output GEMM + Z.
// KV/Ksum partials summed at load. Packed f32x2 mainloops.
// ---------------------------------------------------------------------------
__global__ __launch_bounds__(256) void out_fused(
    const float* __restrict__ x,
    const float* __restrict__ Wq, const float* __restrict__ bq,
    float* __restrict__ out)
{
    const int l0 = blockIdx.x * 128;
    const int n  = blockIdx.y;
    const int h  = blockIdx.z;
    const int nh = n * H + h;
    const int t  = threadIdx.x;
    const int tx = t & 15;
    const int ty = t >> 4;

    float* Qs  = smem;                 // [128][128]  Q tile [l][d]
    float* KVs = Qs + 128 * 128;       // [128][128]  KV transposed [d][m]
    float* xs  = KVs + 128 * 128;      // [128][XS_LD]
    float* Ws  = xs + 128 * XS_LD;     // [16][128]
    float* ks  = Ws + 16 * 128;        // [128]

    // Load KV (= p0 + p1), transposed [m][d] -> KVs[d][m].
    const size_t kvb = (size_t)nh * D * D;
    #pragma unroll
    for (int it = 0; it < 16; it++) {
        int idx = t + it * 256;
        int m = idx >> 5, c4 = idx & 31;
        float4 a = *(const float4*)&g_KVp[kvb + m * D + c4 * 4];
        float4 b = *(const float4*)&g_KVp[(size_t)NJ * H * D * D + kvb + m * D + c4 * 4];
        KVs[(c4 * 4 + 0) * 128 + m] = a.x + b.x;
        KVs[(c4 * 4 + 1) * 128 + m] = a.y + b.y;
        KVs[(c4 * 4 + 2) * 128 + m] = a.z + b.z;
        KVs[(c4 * 4 + 3) * 128 + m] = a.w + b.w;
    }
    if (t < 128)
        ks[t] = g_Ksp[(size_t)nh * D + t] +
                g_Ksp[(size_t)NJ * H * D + nh * D + t];

    // ---- Phase 1: Q tile = elu1(x . Wq_h + bq_h) ----
    {
        float2 acc[8][4];
        #pragma unroll
        for (int i = 0; i < 8; i++)
            #pragma unroll
            for (int j = 0; j < 4; j++) acc[i][j] = make_float2(0.f, 0.f);

        for (int c0 = 0; c0 < C; c0 += 16) {
            __syncthreads();
            #pragma unroll
            for (int it = 0; it < 2; it++) {
                int idx = t + it * 256;
                int row = idx >> 2, c4 = idx & 3;
                float4 v = *(const float4*)
                    &x[((size_t)(l0 + row) * NJ + n) * C + c0 + c4 * 4];
                *(float4*)&xs[row * XS_LD + c4 * 4] = v;
            }
            #pragma unroll
            for (int it = 0; it < 2; it++) {
                int idx = t + it * 256;
                int row = idx >> 5, c4 = idx & 31;
                *(float4*)&Ws[row * 128 + c4 * 4] =
                    *(const float4*)&Wq[(size_t)(c0 + row) * HID + h * D + c4 * 4];
            }
            __syncthreads();

            #pragma unroll
            for (int kk = 0; kk < 16; kk++) {
                float av[8];
                #pragma unroll
                for (int i = 0; i < 8; i++)
                    av[i] = xs[(ty * 8 + i) * XS_LD + kk];
                float4 w0 = *(float4*)&Ws[kk * 128 + tx * 8];
                float4 w1 = *(float4*)&Ws[kk * 128 + tx * 8 + 4];
                float2 b2[4] = { make_float2(w0.x, w0.y), make_float2(w0.z, w0.w),
                                 make_float2(w1.x, w1.y), make_float2(w1.z, w1.w) };
                #pragma unroll
                for (int i = 0; i < 8; i++) {
                    float2 ad = dup2(av[i]);
                    #pragma unroll
                    for (int j = 0; j < 4; j++) fma2(acc[i][j], ad, b2[j]);
                }
            }
        }
        #pragma unroll
        for (int i = 0; i < 8; i++) {
            float vals[8] = { acc[i][0].x, acc[i][0].y, acc[i][1].x, acc[i][1].y,
                              acc[i][2].x, acc[i][2].y, acc[i][3].x, acc[i][3].y };
            float4 o[2];
            float* of = (float*)o;
            #pragma unroll
            for (int j = 0; j < 8; j++)
                of[j] = elu1(vals[j] + bq[h * D + tx * 8 + j]);
            *(float4*)&Qs[(ty * 8 + i) * 128 + tx * 8 + 0] = o[0];
            *(float4*)&Qs[(ty * 8 + i) * 128 + tx * 8 + 4] = o[1];
        }
    }
    __syncthreads();

    // ---- Phase 2: out = Q . KV^T with fused Z ----
    float2 acc2[8][4];
    #pragma unroll
    for (int i = 0; i < 8; i++)
        #pragma unroll
        for (int j = 0; j < 4; j++) acc2[i][j] = make_float2(0.f, 0.f);
    float zacc[8] = {0.f,0.f,0.f,0.f,0.f,0.f,0.f,0.f};

    #pragma unroll 4
    for (int dd = 0; dd < 128; dd++) {
        float av[8];
        #pragma unroll
        for (int i = 0; i < 8; i++)
            av[i] = Qs[(ty * 8 + i) * 128 + dd];
        float4 b0 = *(float4*)&KVs[dd * 128 + tx * 8];
        float4 b1 = *(float4*)&KVs[dd * 128 + tx * 8 + 4];
        float2 b2[4] = { make_float2(b0.x, b0.y), make_float2(b0.z, b0.w),
                         make_float2(b1.x, b1.y), make_float2(b1.z, b1.w) };
        const float kss = ks[dd];
        #pragma unroll
        for (int i = 0; i < 8; i++) {
            zacc[i] += av[i] * kss;
            float2 ad = dup2(av[i]);
            #pragma unroll
            for (int j = 0; j < 4; j++) fma2(acc2[i][j], ad, b2[j]);
        }
    }

    #pragma unroll
    for (int i = 0; i < 8; i++) {
        const float zinv = 1.f / (zacc[i] + 1e-6f);
        const int l = l0 + ty * 8 + i;
        float4 o0 = make_float4(acc2[i][0].x * zinv, acc2[i][0].y * zinv,
                                acc2[i][1].x * zinv, acc2[i][1].y * zinv);
        float4 o1 = make_float4(acc2[i][2].x * zinv, acc2[i][2].y * zinv,
                                acc2[i][3].x * zinv, acc2[i][3].y * zinv);
        size_t base = ((size_t)l * NJ + n) * HID + h * D + tx * 8;
        *(float4*)&out[base + 0] = o0;
        *(float4*)&out[base + 4] = o1;
    }
}

// ---------------------------------------------------------------------------
extern "C" void kernel_launch(void* const* d_in, const int* in_sizes, int n_in,
                              void* d_out, int out_size)
{
    const float* x  = (const float*)d_in[0];
    const float* Wq = (const float*)d_in[1];
    const float* bq = (const float*)d_in[2];
    const float* Wk = (const float*)d_in[3];
    const float* bk = (const float*)d_in[4];
    const float* Wv = (const float*)d_in[5];
    const float* bv = (const float*)d_in[6];
    float* out = (float*)d_out;

    const int smem_a = (128 * XS_LD + 16 * 128 + 2 * 128 * 128) * 4;       // 149504
    const int smem_b = (2 * 128 * 128 + 128 * XS_LD + 16 * 128 + 128) * 4; // 150016

    cudaFuncSetAttribute(kv_fused,  cudaFuncAttributeMaxDynamicSharedMemorySize, smem_a);
    cudaFuncSetAttribute(out_fused, cudaFuncAttributeMaxDynamicSharedMemorySize, smem_b);

    kv_fused<<<dim3(NJ, H, PARTS), 256, smem_a>>>(x, Wk, bk, Wv, bv);
    out_fused<<<dim3(F / 128, NJ, H), 256, smem_b>>>(x, Wq, bq, out);
}

// round 12
// speedup vs baseline: 2.3054x; 2.3054x over previous
#include <cuda_runtime.h>
#include <cuda_bf16.h>
#include <math.h>
#include <stdint.h>

#define F     1024
#define NJ    64
#define C     256
#define HID   1024
#define H     8
#define D     128
#define PARTS 2
#define FCH   8
#define FCPP  (FCH/PARTS)
#define TILE  32768   // [128][128] bf16 swizzled tile

// Pre-split scratch (~134 MB)
__device__ unsigned char g_xh[FCH][NJ][2][TILE];
__device__ unsigned char g_xl[FCH][NJ][2][TILE];
__device__ unsigned char g_Wth[3][H][2][TILE];
__device__ unsigned char g_Wtl[3][H][2][TILE];
__device__ float g_KVp[(size_t)PARTS*NJ*H*D*D];
__device__ float g_Ksp[(size_t)PARTS*NJ*H*D];

extern __shared__ char smem_raw[];

// ===================== helpers =====================
__device__ __forceinline__ uint32_t smem_u32(const void* p) {
    uint32_t a;
    asm("{ .reg .u64 t; cvta.to.shared.u64 t, %1; cvt.u32.u64 %0, t; }" : "=r"(a) : "l"(p));
    return a;
}
__device__ __forceinline__ float elu1(float v) { return (v >= 0.f) ? (v + 1.f) : __expf(v); }

// SW128 swizzled offset in a [128 r][128 c bf16] tile (c even)
__device__ __forceinline__ uint32_t toff(int r, int c) {
    uint32_t b = (uint32_t)(((r >> 3) + (c >> 6) * 16) * 1024 + (r & 7) * 128 + (c & 63) * 2);
    return b ^ ((b >> 3) & 0x70);
}
__device__ __forceinline__ uint32_t rowbase(int r) { return (uint32_t)((r >> 3) * 1024 + (r & 7) * 128); }
__device__ __forceinline__ uint32_t rowmask(int r) { return (uint32_t)((r & 7) << 4); }
// colx2 = col*2 bytes (col in [0,128), multiple of 8)
__device__ __forceinline__ uint32_t coladd(uint32_t colx2, uint32_t mask) {
    return ((colx2 & 128u) ? 16384u : 0u) + ((colx2 & 127u) ^ mask);
}

__device__ __forceinline__ void split2(float v0, float v1, uint32_t& hi, uint32_t& lo) {
    __nv_bfloat16 h0 = __float2bfloat16_rn(v0), h1 = __float2bfloat16_rn(v1);
    float r0 = v0 - __bfloat162float(h0), r1 = v1 - __bfloat162float(h1);
    __nv_bfloat16 l0 = __float2bfloat16_rn(r0), l1 = __float2bfloat16_rn(r1);
    unsigned short uh0 = *(unsigned short*)&h0, uh1 = *(unsigned short*)&h1;
    unsigned short ul0 = *(unsigned short*)&l0, ul1 = *(unsigned short*)&l1;
    hi = (uint32_t)uh0 | ((uint32_t)uh1 << 16);
    lo = (uint32_t)ul0 | ((uint32_t)ul1 << 16);
}
__device__ __forceinline__ float2 unsplit(uint32_t hi, uint32_t lo) {
    unsigned short a0 = hi & 0xFFFF, a1 = hi >> 16, b0 = lo & 0xFFFF, b1 = lo >> 16;
    __nv_bfloat16 *p0 = (__nv_bfloat16*)&a0, *p1 = (__nv_bfloat16*)&a1;
    __nv_bfloat16 *q0 = (__nv_bfloat16*)&b0, *q1 = (__nv_bfloat16*)&b1;
    return make_float2(__bfloat162float(*p0) + __bfloat162float(*q0),
                       __bfloat162float(*p1) + __bfloat162float(*q1));
}

__device__ __forceinline__ void ldsm4(uint32_t r[4], uint32_t a) {
    asm volatile("ldmatrix.sync.aligned.m8n8.x4.shared.b16 {%0,%1,%2,%3}, [%4];"
                 : "=r"(r[0]), "=r"(r[1]), "=r"(r[2]), "=r"(r[3]) : "r"(a));
}
__device__ __forceinline__ void mma16816(float d[4], const uint32_t a[4], uint32_t b0, uint32_t b1) {
    asm volatile(
        "mma.sync.aligned.m16n8k16.row.col.f32.bf16.bf16.f32 "
        "{%0,%1,%2,%3}, {%4,%5,%6,%7}, {%8,%9}, {%0,%1,%2,%3};"
        : "+f"(d[0]), "+f"(d[1]), "+f"(d[2]), "+f"(d[3])
        : "r"(a[0]), "r"(a[1]), "r"(a[2]), "r"(a[3]), "r"(b0), "r"(b1));
}

__device__ __forceinline__ void zero_acc(float a[2][8][4]) {
    #pragma unroll
    for (int i = 0; i < 2; i++)
        #pragma unroll
        for (int j = 0; j < 8; j++)
            #pragma unroll
            for (int q = 0; q < 4; q++) a[i][j][q] = 0.f;
}

// 32KB tile copy, 256 threads
__device__ __forceinline__ void cp_tile(char* dst, const unsigned char* src, int t) {
    uint4* d = (uint4*)dst; const uint4* s = (const uint4*)src;
    #pragma unroll
    for (int j = 0; j < 8; j++) d[t + j * 256] = s[t + j * 256];
}

// Warp GEMM: acc[128x128 tile slice] += A(hi+lo) x B(hi+lo)^T over k=128.
// A rows m, B rows n, both [.][k] row-major swizzled tiles. 3 hi/lo combos.
// Warp tile: 32(m) x 64(n); mw in {0,32,64,96}, nw in {0,64}.
__device__ void wgemm128(float acc[2][8][4],
                         uint32_t AH, uint32_t AL, uint32_t BH, uint32_t BL,
                         int mw, int nw, int lane)
{
    const int phase = lane >> 3, lr = lane & 7;
    const int arow0 = mw + ((phase & 1) << 3) + lr;
    const uint32_t ab0 = rowbase(arow0), am0 = rowmask(arow0);
    const uint32_t ab1 = rowbase(arow0 + 16), am1 = rowmask(arow0 + 16);
    const int acol = (phase >> 1) << 3;
    const int brow_off = ((phase >> 1) << 3) + lr;
    const int bcol = (phase & 1) << 3;
    uint32_t bb[4], bm[4];
    #pragma unroll
    for (int i = 0; i < 4; i++) {
        int r = nw + i * 16 + brow_off;
        bb[i] = rowbase(r); bm[i] = rowmask(r);
    }

    #pragma unroll
    for (int k = 0; k < 8; k++) {
        uint32_t ah0[4], ah1[4], al0[4], al1[4];
        uint32_t ca = (uint32_t)((k * 16 + acol) * 2);
        uint32_t oA0 = ab0 + coladd(ca, am0);
        uint32_t oA1 = ab1 + coladd(ca, am1);
        ldsm4(ah0, AH + oA0); ldsm4(ah1, AH + oA1);
        ldsm4(al0, AL + oA0); ldsm4(al1, AL + oA1);
        uint32_t bh[4][4], bl[4][4];
        uint32_t cb = (uint32_t)((k * 16 + bcol) * 2);
        #pragma unroll
        for (int i = 0; i < 4; i++) {
            uint32_t o = coladd(cb, bm[i]) + bb[i];
            ldsm4(bh[i], BH + o);
            ldsm4(bl[i], BL + o);
        }
        #pragma unroll
        for (int nt = 0; nt < 8; nt++) {
            uint32_t b0h = bh[nt >> 1][(nt & 1) * 2], b1h = bh[nt >> 1][(nt & 1) * 2 + 1];
            uint32_t b0l = bl[nt >> 1][(nt & 1) * 2], b1l = bl[nt >> 1][(nt & 1) * 2 + 1];
            mma16816(acc[0][nt], ah0, b0h, b1h);
            mma16816(acc[0][nt], ah0, b0l, b1l);
            mma16816(acc[0][nt], al0, b0h, b1h);
            mma16816(acc[1][nt], ah1, b0h, b1h);
            mma16816(acc[1][nt], ah1, b0l, b1l);
            mma16816(acc[1][nt], al1, b0h, b1h);
        }
    }
}

// ===================== prep kernels =====================
__global__ __launch_bounds__(128) void prep_x(const float* __restrict__ x) {
    const int fc = blockIdx.x, n = blockIdx.y, cc = blockIdx.z;
    const int t = threadIdx.x, cp = t & 63, rh = t >> 6;
    unsigned char* dh = &g_xh[fc][n][cc][0];
    unsigned char* dl = &g_xl[fc][n][cc][0];
    for (int jj = 0; jj < 64; jj++) {
        int f = jj * 2 + rh;
        float2 v = *(const float2*)&x[((size_t)(fc * 128 + f) * NJ + n) * C + cc * 128 + 2 * cp];
        uint32_t hi, lo; split2(v.x, v.y, hi, lo);
        uint32_t o = toff(f, 2 * cp);
        *(uint32_t*)(dh + o) = hi;
        *(uint32_t*)(dl + o) = lo;
    }
}
__global__ __launch_bounds__(128) void prep_w(
    const float* __restrict__ Wq, const float* __restrict__ Wk, const float* __restrict__ Wv) {
    const int z = blockIdx.x, h = blockIdx.y, cc = blockIdx.z;
    const float* W = (z == 0) ? Wq : (z == 1) ? Wk : Wv;
    const int t = threadIdx.x, cp = t & 63, rh = t >> 6;
    unsigned char* dh = &g_Wth[z][h][cc][0];
    unsigned char* dl = &g_Wtl[z][h][cc][0];
    for (int jj = 0; jj < 64; jj++) {
        int o = jj * 2 + rh;
        float w0 = W[(size_t)(cc * 128 + 2 * cp) * HID + h * D + o];
        float w1 = W[(size_t)(cc * 128 + 2 * cp + 1) * HID + h * D + o];
        uint32_t hi, lo; split2(w0, w1, hi, lo);
        uint32_t off = toff(o, 2 * cp);
        *(uint32_t*)(dh + off) = hi;
        *(uint32_t*)(dl + off) = lo;
    }
}

// ===================== kernel A: K/V proj + KV accumulation =====================
// grid (NJ, H, PARTS), 256 threads. Slots: 0/1 work-A (W, later Vt), 2/3 work-B (x), 4/5 Kt.
__global__ __launch_bounds__(256, 1) void kv_mma(
    const float* __restrict__ bk, const float* __restrict__ bv)
{
    const int n = blockIdx.x, h = blockIdx.y, p = blockIdx.z;
    const int t = threadIdx.x, lane = t & 31, w = t >> 5;
    const int mw = (w >> 1) * 32, nw = (w & 1) * 64;
    char* sm = smem_raw;
    const uint32_t su = smem_u32(smem_raw);
    float* aux = (float*)(sm + 6 * TILE);   // [0..127] bk, [128..255] bv, [256..383] ksum partial

    if (t < 128) { aux[t] = bk[h * D + t]; aux[128 + t] = bv[h * D + t]; aux[256 + t] = 0.f; }

    float kvac[2][8][4]; zero_acc(kvac);
    float ksum = 0.f;
    __syncthreads();

    for (int fi = 0; fi < FCPP; fi++) {
        const int fc = p * FCPP + fi;

        // ---- K projection: Kt[d][f] ----
        float pr[2][8][4]; zero_acc(pr);
        #pragma unroll 1
        for (int cc = 0; cc < 2; cc++) {
            __syncthreads();
            cp_tile(sm,            &g_Wth[1][h][cc][0], t);
            cp_tile(sm + TILE,     &g_Wtl[1][h][cc][0], t);
            cp_tile(sm + 2 * TILE, &g_xh[fc][n][cc][0], t);
            cp_tile(sm + 3 * TILE, &g_xl[fc][n][cc][0], t);
            __syncthreads();
            wgemm128(pr, su, su + TILE, su + 2 * TILE, su + 3 * TILE, mw, nw, lane);
        }
        // K epilogue: bias + elu + split -> slots 4/5; ksum partials via smem atomics
        #pragma unroll
        for (int mt = 0; mt < 2; mt++) {
            const int r0 = mw + mt * 16 + (lane >> 2), r1 = r0 + 8;
            const float bs0 = aux[r0], bs1 = aux[r1];
            float s0 = 0.f, s1 = 0.f;
            #pragma unroll
            for (int nt = 0; nt < 8; nt++) {
                const int c = nw + nt * 8 + 2 * (lane & 3);
                float v00 = elu1(pr[mt][nt][0] + bs0), v01 = elu1(pr[mt][nt][1] + bs0);
                float v10 = elu1(pr[mt][nt][2] + bs1), v11 = elu1(pr[mt][nt][3] + bs1);
                s0 += v00 + v01; s1 += v10 + v11;
                uint32_t hi, lo;
                split2(v00, v01, hi, lo);
                *(uint32_t*)(sm + 4 * TILE + toff(r0, c)) = hi;
                *(uint32_t*)(sm + 5 * TILE + toff(r0, c)) = lo;
                split2(v10, v11, hi, lo);
                *(uint32_t*)(sm + 4 * TILE + toff(r1, c)) = hi;
                *(uint32_t*)(sm + 5 * TILE + toff(r1, c)) = lo;
            }
            s0 += __shfl_xor_sync(0xFFFFFFFFu, s0, 1); s0 += __shfl_xor_sync(0xFFFFFFFFu, s0, 2);
            s1 += __shfl_xor_sync(0xFFFFFFFFu, s1, 1); s1 += __shfl_xor_sync(0xFFFFFFFFu, s1, 2);
            if ((lane & 3) == 0) { atomicAdd(&aux[256 + r0], s0); atomicAdd(&aux[256 + r1], s1); }
        }

        // ---- V projection: Vt[m][f] ----
        zero_acc(pr);
        #pragma unroll 1
        for (int cc = 0; cc < 2; cc++) {
            __syncthreads();
            cp_tile(sm,            &g_Wth[2][h][cc][0], t);
            cp_tile(sm + TILE,     &g_Wtl[2][h][cc][0], t);
            cp_tile(sm + 2 * TILE, &g_xh[fc][n][cc][0], t);
            cp_tile(sm + 3 * TILE, &g_xl[fc][n][cc][0], t);
            __syncthreads();
            wgemm128(pr, su, su + TILE, su + 2 * TILE, su + 3 * TILE, mw, nw, lane);
        }
        __syncthreads();   // everyone done reading slots 0/1 before Vt overwrites them
        #pragma unroll
        for (int mt = 0; mt < 2; mt++) {
            const int r0 = mw + mt * 16 + (lane >> 2), r1 = r0 + 8;
            const float bs0 = aux[128 + r0], bs1 = aux[128 + r1];
            #pragma unroll
            for (int nt = 0; nt < 8; nt++) {
                const int c = nw + nt * 8 + 2 * (lane & 3);
                uint32_t hi, lo;
                split2(pr[mt][nt][0] + bs0, pr[mt][nt][1] + bs0, hi, lo);
                *(uint32_t*)(sm + toff(r0, c))        = hi;
                *(uint32_t*)(sm + TILE + toff(r0, c)) = lo;
                split2(pr[mt][nt][2] + bs1, pr[mt][nt][3] + bs1, hi, lo);
                *(uint32_t*)(sm + toff(r1, c))        = hi;
                *(uint32_t*)(sm + TILE + toff(r1, c)) = lo;
            }
        }
        __syncthreads();   // Vt visible; ksum atomics drained
        if (t < 128) { ksum += aux[256 + t]; aux[256 + t] = 0.f; }

        // ---- KV[m][d] += Vt x Kt^T over f ----
        wgemm128(kvac, su, su + TILE, su + 4 * TILE, su + 5 * TILE, mw, nw, lane);
    }

    // write KV partial + Ksum partial
    const int nh = n * H + h;
    const size_t kvb = ((size_t)p * NJ * H + nh) * (size_t)(D * D);
    #pragma unroll
    for (int mt = 0; mt < 2; mt++) {
        const int r0 = mw + mt * 16 + (lane >> 2), r1 = r0 + 8;
        #pragma unroll
        for (int nt = 0; nt < 8; nt++) {
            const int c = nw + nt * 8 + 2 * (lane & 3);
            *(float2*)&g_KVp[kvb + (size_t)r0 * D + c] = make_float2(kvac[mt][nt][0], kvac[mt][nt][1]);
            *(float2*)&g_KVp[kvb + (size_t)r1 * D + c] = make_float2(kvac[mt][nt][2], kvac[mt][nt][3]);
        }
    }
    if (t < 128) g_Ksp[((size_t)p * NJ * H + nh) * D + t] = ksum;
}

// ===================== kernel B: Q proj + output GEMM + Z =====================
// grid (F/128, NJ, H), 256 threads. Slots: 0/1 x -> KV, 2/3 Wq, 4/5 Q.
__global__ __launch_bounds__(256, 1) void out_mma(
    const float* __restrict__ bq, float* __restrict__ out)
{
    const int fc = blockIdx.x, n = blockIdx.y, h = blockIdx.z;
    const int nh = n * H + h;
    const int t = threadIdx.x, lane = t & 31, w = t >> 5;
    const int mw = (w >> 1) * 32, nw = (w & 1) * 64;
    char* sm = smem_raw;
    const uint32_t su = smem_u32(smem_raw);
    float* aux = (float*)(sm + 6 * TILE);   // [0..127] bq, [128..255] ks, [256..383] zinv

    if (t < 128) {
        aux[t] = bq[h * D + t];
        aux[128 + t] = g_Ksp[(size_t)nh * D + t] + g_Ksp[(size_t)NJ * H * D + (size_t)nh * D + t];
    }

    // ---- Q projection: Q[l][d] = x . Wq^T ----
    float pr[2][8][4]; zero_acc(pr);
    #pragma unroll 1
    for (int cc = 0; cc < 2; cc++) {
        __syncthreads();
        cp_tile(sm,            &g_xh[fc][n][cc][0], t);
        cp_tile(sm + TILE,     &g_xl[fc][n][cc][0], t);
        cp_tile(sm + 2 * TILE, &g_Wth[0][h][cc][0], t);
        cp_tile(sm + 3 * TILE, &g_Wtl[0][h][cc][0], t);
        __syncthreads();
        wgemm128(pr, su, su + TILE, su + 2 * TILE, su + 3 * TILE, mw, nw, lane);
    }
    // Q epilogue: bias (by column d) + elu + split -> slots 4/5
    #pragma unroll
    for (int mt = 0; mt < 2; mt++) {
        const int r0 = mw + mt * 16 + (lane >> 2), r1 = r0 + 8;
        #pragma unroll
        for (int nt = 0; nt < 8; nt++) {
            const int c = nw + nt * 8 + 2 * (lane & 3);
            const float b0 = aux[c], b1 = aux[c + 1];
            uint32_t hi, lo;
            split2(elu1(pr[mt][nt][0] + b0), elu1(pr[mt][nt][1] + b1), hi, lo);
            *(uint32_t*)(sm + 4 * TILE + toff(r0, c)) = hi;
            *(uint32_t*)(sm + 5 * TILE + toff(r0, c)) = lo;
            split2(elu1(pr[mt][nt][2] + b0), elu1(pr[mt][nt][3] + b1), hi, lo);
            *(uint32_t*)(sm + 4 * TILE + toff(r1, c)) = hi;
            *(uint32_t*)(sm + 5 * TILE + toff(r1, c)) = lo;
        }
    }
    __syncthreads();   // Q visible; slots 0/1 free

    // ---- load KV (sum partials) -> slots 0/1 ----
    {
        const size_t kvb  = (size_t)nh * (size_t)(D * D);
        const size_t kvb2 = (size_t)NJ * H * D * D + kvb;
        #pragma unroll 4
        for (int j = 0; j < 32; j++) {
            int flat = j * 256 + t;
            int m = flat >> 6, cp2 = flat & 63;
            float2 a = *(const float2*)&g_KVp[kvb  + (size_t)m * D + 2 * cp2];
            float2 b = *(const float2*)&g_KVp[kvb2 + (size_t)m * D + 2 * cp2];
            uint32_t hi, lo; split2(a.x + b.x, a.y + b.y, hi, lo);
            uint32_t o = toff(m, 2 * cp2);
            *(uint32_t*)(sm + o)        = hi;
            *(uint32_t*)(sm + TILE + o) = lo;
        }
    }
    // ---- Z denominator per l ----
    if (t < 128) {
        float za = 0.f;
        #pragma unroll 8
        for (int j = 0; j < 64; j++) {
            uint32_t o = toff(t, 2 * j);
            float2 q = unsplit(*(uint32_t*)(sm + 4 * TILE + o), *(uint32_t*)(sm + 5 * TILE + o));
            za += q.x * aux[128 + 2 * j] + q.y * aux[128 + 2 * j + 1];
        }
        aux[256 + t] = 1.f / (za + 1e-6f);
    }
    __syncthreads();

    // ---- out[l][m] = Q x KV^T over d ----
    zero_acc(pr);
    wgemm128(pr, su + 4 * TILE, su + 5 * TILE, su, su + TILE, mw, nw, lane);

    // epilogue: apply zinv, write global
    #pragma unroll
    for (int mt = 0; mt < 2; mt++) {
        const int r0 = mw + mt * 16 + (lane >> 2), r1 = r0 + 8;
        const float z0 = aux[256 + r0], z1 = aux[256 + r1];
        const size_t ob0 = ((size_t)(fc * 128 + r0) * NJ + n) * HID + h * D;
        const size_t ob1 = ((size_t)(fc * 128 + r1) * NJ + n) * HID + h * D;
        #pragma unroll
        for (int nt = 0; nt < 8; nt++) {
            const int c = nw + nt * 8 + 2 * (lane & 3);
            *(float2*)&out[ob0 + c] = make_float2(pr[mt][nt][0] * z0, pr[mt][nt][1] * z0);
            *(float2*)&out[ob1 + c] = make_float2(pr[mt][nt][2] * z1, pr[mt][nt][3] * z1);
        }
    }
}

// ===================== launch =====================
extern "C" void kernel_launch(void* const* d_in, const int* in_sizes, int n_in,
                              void* d_out, int out_size) {
    const float* x  = (const float*)d_in[0];
    const float* Wq = (const float*)d_in[1];
    const float* bq = (const float*)d_in[2];
    const float* Wk = (const float*)d_in[3];
    const float* bk = (const float*)d_in[4];
    const float* Wv = (const float*)d_in[5];
    const float* bv = (const float*)d_in[6];
    float* out = (float*)d_out;

    const int smem_sz = 6 * TILE + 1536;   // 198144
    cudaFuncSetAttribute(kv_mma,  cudaFuncAttributeMaxDynamicSharedMemorySize, smem_sz);
    cudaFuncSetAttribute(out_mma, cudaFuncAttributeMaxDynamicSharedMemorySize, smem_sz);

    prep_x<<<dim3(FCH, NJ, 2), 128>>>(x);
    prep_w<<<dim3(3, H, 2), 128>>>(Wq, Wk, Wv);
    kv_mma<<<dim3(NJ, H, PARTS), 256, smem_sz>>>(bk, bv);
    out_mma<<<dim3(F / 128, NJ, H), 256, smem_sz>>>(bq, out);
}

// round 14
// speedup vs baseline: 2.5438x; 1.1034x over previous
#include <cuda_runtime.h>
#include <cuda_bf16.h>
#include <math.h>
#include <stdint.h>

#define F     1024
#define NJ    64
#define C     256
#define HID   1024
#define H     8
#define D     128
#define PARTS 2
#define FCH   8
#define FCPP  (FCH/PARTS)
#define TILE  32768   // [128][128] bf16 swizzled tile
#define NT    512     // threads per MMA block

// Pre-split scratch (~134 MB)
__device__ unsigned char g_xh[FCH][NJ][2][TILE];
__device__ unsigned char g_xl[FCH][NJ][2][TILE];
__device__ unsigned char g_Wth[3][H][2][TILE];
__device__ unsigned char g_Wtl[3][H][2][TILE];
__device__ float g_KVp[(size_t)PARTS*NJ*H*D*D];
__device__ float g_Ksp[(size_t)PARTS*NJ*H*D];

extern __shared__ char smem_raw[];

// ===================== helpers =====================
__device__ __forceinline__ uint32_t smem_u32(const void* p) {
    uint32_t a;
    asm("{ .reg .u64 t; cvta.to.shared.u64 t, %1; cvt.u32.u64 %0, t; }" : "=r"(a) : "l"(p));
    return a;
}
__device__ __forceinline__ float elu1(float v) { return (v >= 0.f) ? (v + 1.f) : __expf(v); }

// SW128 swizzled offset in a [128 r][128 c bf16] tile (c even)
__device__ __forceinline__ uint32_t toff(int r, int c) {
    uint32_t b = (uint32_t)(((r >> 3) + (c >> 6) * 16) * 1024 + (r & 7) * 128 + (c & 63) * 2);
    return b ^ ((b >> 3) & 0x70);
}
__device__ __forceinline__ uint32_t rowbase(int r) { return (uint32_t)((r >> 3) * 1024 + (r & 7) * 128); }
__device__ __forceinline__ uint32_t rowmask(int r) { return (uint32_t)((r & 7) << 4); }
__device__ __forceinline__ uint32_t coladd(uint32_t colx2, uint32_t mask) {
    return ((colx2 & 128u) ? 16384u : 0u) + ((colx2 & 127u) ^ mask);
}

__device__ __forceinline__ void split2(float v0, float v1, uint32_t& hi, uint32_t& lo) {
    __nv_bfloat16 h0 = __float2bfloat16_rn(v0), h1 = __float2bfloat16_rn(v1);
    float r0 = v0 - __bfloat162float(h0), r1 = v1 - __bfloat162float(h1);
    __nv_bfloat16 l0 = __float2bfloat16_rn(r0), l1 = __float2bfloat16_rn(r1);
    unsigned short uh0 = *(unsigned short*)&h0, uh1 = *(unsigned short*)&h1;
    unsigned short ul0 = *(unsigned short*)&l0, ul1 = *(unsigned short*)&l1;
    hi = (uint32_t)uh0 | ((uint32_t)uh1 << 16);
    lo = (uint32_t)ul0 | ((uint32_t)ul1 << 16);
}
__device__ __forceinline__ float2 unsplit(uint32_t hi, uint32_t lo) {
    unsigned short a0 = hi & 0xFFFF, a1 = hi >> 16, b0 = lo & 0xFFFF, b1 = lo >> 16;
    __nv_bfloat16 *p0 = (__nv_bfloat16*)&a0, *p1 = (__nv_bfloat16*)&a1;
    __nv_bfloat16 *q0 = (__nv_bfloat16*)&b0, *q1 = (__nv_bfloat16*)&b1;
    return make_float2(__bfloat162float(*p0) + __bfloat162float(*q0),
                       __bfloat162float(*p1) + __bfloat162float(*q1));
}

__device__ __forceinline__ void ldsm4(uint32_t r[4], uint32_t a) {
    asm volatile("ldmatrix.sync.aligned.m8n8.x4.shared.b16 {%0,%1,%2,%3}, [%4];"
                 : "=r"(r[0]), "=r"(r[1]), "=r"(r[2]), "=r"(r[3]) : "r"(a));
}
__device__ __forceinline__ void mma16816(float d[4], const uint32_t a[4], uint32_t b0, uint32_t b1) {
    asm volatile(
        "mma.sync.aligned.m16n8k16.row.col.f32.bf16.bf16.f32 "
        "{%0,%1,%2,%3}, {%4,%5,%6,%7}, {%8,%9}, {%0,%1,%2,%3};"
        : "+f"(d[0]), "+f"(d[1]), "+f"(d[2]), "+f"(d[3])
        : "r"(a[0]), "r"(a[1]), "r"(a[2]), "r"(a[3]), "r"(b0), "r"(b1));
}

__device__ __forceinline__ void zero_acc(float a[2][4][4]) {
    #pragma unroll
    for (int i = 0; i < 2; i++)
        #pragma unroll
        for (int j = 0; j < 4; j++)
            #pragma unroll
            for (int q = 0; q < 4; q++) a[i][j][q] = 0.f;
}

// 32KB tile copy, NT threads
__device__ __forceinline__ void cp_tile(char* dst, const unsigned char* src, int t) {
    uint4* d = (uint4*)dst; const uint4* s = (const uint4*)src;
    #pragma unroll
    for (int j = 0; j < 2048 / NT; j++) d[t + j * NT] = s[t + j * NT];
}

// Warp GEMM: acc (32m x 32n slice) += A(hi+lo) x B(hi+lo)^T over k=128.
// Both operands [.][k] row-major swizzled tiles; 3 hi/lo combos.
// 16 warps: mw in {0,32,64,96}, nw in {0,32,64,96}.
__device__ void wgemm(float acc[2][4][4],
                      uint32_t AH, uint32_t AL, uint32_t BH, uint32_t BL,
                      int mw, int nw, int lane)
{
    const int phase = lane >> 3, lr = lane & 7;
    const int arow0 = mw + ((phase & 1) << 3) + lr;
    const uint32_t ab0 = rowbase(arow0), am0 = rowmask(arow0);
    const uint32_t ab1 = rowbase(arow0 + 16), am1 = rowmask(arow0 + 16);
    const int acol = (phase >> 1) << 3;
    const int brow_off = ((phase >> 1) << 3) + lr;
    const int bcol = (phase & 1) << 3;
    uint32_t bb[2], bm[2];
    #pragma unroll
    for (int i = 0; i < 2; i++) {
        int r = nw + i * 16 + brow_off;
        bb[i] = rowbase(r); bm[i] = rowmask(r);
    }

    #pragma unroll
    for (int k = 0; k < 8; k++) {
        uint32_t ah0[4], ah1[4], al0[4], al1[4];
        uint32_t ca = (uint32_t)((k * 16 + acol) * 2);
        uint32_t oA0 = ab0 + coladd(ca, am0);
        uint32_t oA1 = ab1 + coladd(ca, am1);
        ldsm4(ah0, AH + oA0); ldsm4(ah1, AH + oA1);
        ldsm4(al0, AL + oA0); ldsm4(al1, AL + oA1);
        uint32_t bh[2][4], bl[2][4];
        uint32_t cb = (uint32_t)((k * 16 + bcol) * 2);
        #pragma unroll
        for (int i = 0; i < 2; i++) {
            uint32_t o = coladd(cb, bm[i]) + bb[i];
            ldsm4(bh[i], BH + o);
            ldsm4(bl[i], BL + o);
        }
        #pragma unroll
        for (int nt = 0; nt < 4; nt++) {
            uint32_t b0h = bh[nt >> 1][(nt & 1) * 2], b1h = bh[nt >> 1][(nt & 1) * 2 + 1];
            uint32_t b0l = bl[nt >> 1][(nt & 1) * 2], b1l = bl[nt >> 1][(nt & 1) * 2 + 1];
            mma16816(acc[0][nt], ah0, b0h, b1h);
            mma16816(acc[0][nt], ah0, b0l, b1l);
            mma16816(acc[0][nt], al0, b0h, b1h);
            mma16816(acc[1][nt], ah1, b0h, b1h);
            mma16816(acc[1][nt], ah1, b0l, b1l);
            mma16816(acc[1][nt], al1, b0h, b1h);
        }
    }
}

// ===================== prep kernels =====================
__global__ __launch_bounds__(128) void prep_x(const float* __restrict__ x) {
    const int fc = blockIdx.x, n = blockIdx.y, cc = blockIdx.z;
    const int t = threadIdx.x, cp = t & 63, rh = t >> 6;
    unsigned char* dh = &g_xh[fc][n][cc][0];
    unsigned char* dl = &g_xl[fc][n][cc][0];
    for (int jj = 0; jj < 64; jj++) {
        int f = jj * 2 + rh;
        float2 v = *(const float2*)&x[((size_t)(fc * 128 + f) * NJ + n) * C + cc * 128 + 2 * cp];
        uint32_t hi, lo; split2(v.x, v.y, hi, lo);
        uint32_t o = toff(f, 2 * cp);
        *(uint32_t*)(dh + o) = hi;
        *(uint32_t*)(dl + o) = lo;
    }
}
__global__ __launch_bounds__(128) void prep_w(
    const float* __restrict__ Wq, const float* __restrict__ Wk, const float* __restrict__ Wv) {
    const int z = blockIdx.x, h = blockIdx.y, cc = blockIdx.z;
    const float* W = (z == 0) ? Wq : (z == 1) ? Wk : Wv;
    const int t = threadIdx.x, cp = t & 63, rh = t >> 6;
    unsigned char* dh = &g_Wth[z][h][cc][0];
    unsigned char* dl = &g_Wtl[z][h][cc][0];
    for (int jj = 0; jj < 64; jj++) {
        int o = jj * 2 + rh;
        float w0 = W[(size_t)(cc * 128 + 2 * cp) * HID + h * D + o];
        float w1 = W[(size_t)(cc * 128 + 2 * cp + 1) * HID + h * D + o];
        uint32_t hi, lo; split2(w0, w1, hi, lo);
        uint32_t off = toff(o, 2 * cp);
        *(uint32_t*)(dh + off) = hi;
        *(uint32_t*)(dl + off) = lo;
    }
}

// ===================== kernel A: K/V proj + KV accumulation =====================
// grid (NJ, H, PARTS), NT threads. Slots: 0/1 work-A (W, later Vt), 2/3 work-B (x), 4/5 Kt.
__global__ __launch_bounds__(NT, 1) void kv_mma(
    const float* __restrict__ bk, const float* __restrict__ bv)
{
    const int n = blockIdx.x, h = blockIdx.y, p = blockIdx.z;
    const int t = threadIdx.x, lane = t & 31, w = t >> 5;
    const int mw = (w >> 2) * 32, nw = (w & 3) * 32;
    char* sm = smem_raw;
    const uint32_t su = smem_u32(smem_raw);
    float* aux = (float*)(sm + 6 * TILE);   // [0..127] bk, [128..255] bv, [256..383] ksum partial

    if (t < 128) { aux[t] = bk[h * D + t]; aux[128 + t] = bv[h * D + t]; aux[256 + t] = 0.f; }

    float kvac[2][4][4]; zero_acc(kvac);
    float ksum = 0.f;
    __syncthreads();

    for (int fi = 0; fi < FCPP; fi++) {
        const int fc = p * FCPP + fi;

        // ---- K projection: Kt[d][f] ----
        float pr[2][4][4]; zero_acc(pr);
        #pragma unroll 1
        for (int cc = 0; cc < 2; cc++) {
            __syncthreads();
            cp_tile(sm,            &g_Wth[1][h][cc][0], t);
            cp_tile(sm + TILE,     &g_Wtl[1][h][cc][0], t);
            cp_tile(sm + 2 * TILE, &g_xh[fc][n][cc][0], t);
            cp_tile(sm + 3 * TILE, &g_xl[fc][n][cc][0], t);
            __syncthreads();
            wgemm(pr, su, su + TILE, su + 2 * TILE, su + 3 * TILE, mw, nw, lane);
        }
        // K epilogue: bias + elu + split -> slots 4/5; ksum partials via smem atomics
        #pragma unroll
        for (int mt = 0; mt < 2; mt++) {
            const int r0 = mw + mt * 16 + (lane >> 2), r1 = r0 + 8;
            const float bs0 = aux[r0], bs1 = aux[r1];
            float s0 = 0.f, s1 = 0.f;
            #pragma unroll
            for (int nt = 0; nt < 4; nt++) {
                const int c = nw + nt * 8 + 2 * (lane & 3);
                float v00 = elu1(pr[mt][nt][0] + bs0), v01 = elu1(pr[mt][nt][1] + bs0);
                float v10 = elu1(pr[mt][nt][2] + bs1), v11 = elu1(pr[mt][nt][3] + bs1);
                s0 += v00 + v01; s1 += v10 + v11;
                uint32_t hi, lo;
                split2(v00, v01, hi, lo);
                *(uint32_t*)(sm + 4 * TILE + toff(r0, c)) = hi;
                *(uint32_t*)(sm + 5 * TILE + toff(r0, c)) = lo;
                split2(v10, v11, hi, lo);
                *(uint32_t*)(sm + 4 * TILE + toff(r1, c)) = hi;
                *(uint32_t*)(sm + 5 * TILE + toff(r1, c)) = lo;
            }
            s0 += __shfl_xor_sync(0xFFFFFFFFu, s0, 1); s0 += __shfl_xor_sync(0xFFFFFFFFu, s0, 2);
            s1 += __shfl_xor_sync(0xFFFFFFFFu, s1, 1); s1 += __shfl_xor_sync(0xFFFFFFFFu, s1, 2);
            if ((lane & 3) == 0) { atomicAdd(&aux[256 + r0], s0); atomicAdd(&aux[256 + r1], s1); }
        }

        // ---- V projection: Vt[m][f] ----
        zero_acc(pr);
        #pragma unroll 1
        for (int cc = 0; cc < 2; cc++) {
            __syncthreads();
            cp_tile(sm,            &g_Wth[2][h][cc][0], t);
            cp_tile(sm + TILE,     &g_Wtl[2][h][cc][0], t);
            cp_tile(sm + 2 * TILE, &g_xh[fc][n][cc][0], t);
            cp_tile(sm + 3 * TILE, &g_xl[fc][n][cc][0], t);
            __syncthreads();
            wgemm(pr, su, su + TILE, su + 2 * TILE, su + 3 * TILE, mw, nw, lane);
        }
        __syncthreads();   // everyone done reading slots 0/1 before Vt overwrites them
        #pragma unroll
        for (int mt = 0; mt < 2; mt++) {
            const int r0 = mw + mt * 16 + (lane >> 2), r1 = r0 + 8;
            const float bs0 = aux[128 + r0], bs1 = aux[128 + r1];
            #pragma unroll
            for (int nt = 0; nt < 4; nt++) {
                const int c = nw + nt * 8 + 2 * (lane & 3);
                uint32_t hi, lo;
                split2(pr[mt][nt][0] + bs0, pr[mt][nt][1] + bs0, hi, lo);
                *(uint32_t*)(sm + toff(r0, c))        = hi;
                *(uint32_t*)(sm + TILE + toff(r0, c)) = lo;
                split2(pr[mt][nt][2] + bs1, pr[mt][nt][3] + bs1, hi, lo);
                *(uint32_t*)(sm + toff(r1, c))        = hi;
                *(uint32_t*)(sm + TILE + toff(r1, c)) = lo;
            }
        }
        __syncthreads();   // Vt visible; ksum atomics drained
        if (t < 128) { ksum += aux[256 + t]; aux[256 + t] = 0.f; }

        // ---- KV[m][d] += Vt x Kt^T over f ----
        wgemm(kvac, su, su + TILE, su + 4 * TILE, su + 5 * TILE, mw, nw, lane);
    }

    // write KV partial + Ksum partial
    const int nh = n * H + h;
    const size_t kvb = ((size_t)p * NJ * H + nh) * (size_t)(D * D);
    #pragma unroll
    for (int mt = 0; mt < 2; mt++) {
        const int r0 = mw + mt * 16 + (lane >> 2), r1 = r0 + 8;
        #pragma unroll
        for (int nt = 0; nt < 4; nt++) {
            const int c = nw + nt * 8 + 2 * (lane & 3);
            *(float2*)&g_KVp[kvb + (size_t)r0 * D + c] = make_float2(kvac[mt][nt][0], kvac[mt][nt][1]);
            *(float2*)&g_KVp[kvb + (size_t)r1 * D + c] = make_float2(kvac[mt][nt][2], kvac[mt][nt][3]);
        }
    }
    if (t < 128) g_Ksp[((size_t)p * NJ * H + nh) * D + t] = ksum;
}

// ===================== kernel B: Q proj + output GEMM + Z =====================
// grid (F/128, NJ, H), NT threads. Slots: 0/1 x -> KV, 2/3 Wq, 4/5 Q.
__global__ __launch_bounds__(NT, 1) void out_mma(
    const float* __restrict__ bq, float* __restrict__ out)
{
    const int fc = blockIdx.x, n = blockIdx.y, h = blockIdx.z;
    const int nh = n * H + h;
    const int t = threadIdx.x, lane = t & 31, w = t >> 5;
    const int mw = (w >> 2) * 32, nw = (w & 3) * 32;
    char* sm = smem_raw;
    const uint32_t su = smem_u32(smem_raw);
    float* aux = (float*)(sm + 6 * TILE);   // [0..127] bq, [128..255] ks, [256..383] zinv

    if (t < 128) {
        aux[t] = bq[h * D + t];
        aux[128 + t] = g_Ksp[(size_t)nh * D + t] + g_Ksp[(size_t)NJ * H * D + (size_t)nh * D + t];
    }

    // ---- Q projection: Q[l][d] = x . Wq^T ----
    float pr[2][4][4]; zero_acc(pr);
    #pragma unroll 1
    for (int cc = 0; cc < 2; cc++) {
        __syncthreads();
        cp_tile(sm,            &g_xh[fc][n][cc][0], t);
        cp_tile(sm + TILE,     &g_xl[fc][n][cc][0], t);
        cp_tile(sm + 2 * TILE, &g_Wth[0][h][cc][0], t);
        cp_tile(sm + 3 * TILE, &g_Wtl[0][h][cc][0], t);
        __syncthreads();
        wgemm(pr, su, su + TILE, su + 2 * TILE, su + 3 * TILE, mw, nw, lane);
    }
    // Q epilogue: bias (by column d) + elu + split -> slots 4/5
    #pragma unroll
    for (int mt = 0; mt < 2; mt++) {
        const int r0 = mw + mt * 16 + (lane >> 2), r1 = r0 + 8;
        #pragma unroll
        for (int nt = 0; nt < 4; nt++) {
            const int c = nw + nt * 8 + 2 * (lane & 3);
            const float b0 = aux[c], b1 = aux[c + 1];
            uint32_t hi, lo;
            split2(elu1(pr[mt][nt][0] + b0), elu1(pr[mt][nt][1] + b1), hi, lo);
            *(uint32_t*)(sm + 4 * TILE + toff(r0, c)) = hi;
            *(uint32_t*)(sm + 5 * TILE + toff(r0, c)) = lo;
            split2(elu1(pr[mt][nt][2] + b0), elu1(pr[mt][nt][3] + b1), hi, lo);
            *(uint32_t*)(sm + 4 * TILE + toff(r1, c)) = hi;
            *(uint32_t*)(sm + 5 * TILE + toff(r1, c)) = lo;
        }
    }
    __syncthreads();   // Q visible; slots 0/1 free

    // ---- load KV (sum partials) -> slots 0/1 ----
    {
        const size_t kvb  = (size_t)nh * (size_t)(D * D);
        const size_t kvb2 = (size_t)NJ * H * D * D + kvb;
        #pragma unroll 4
        for (int j = 0; j < 8192 / NT; j++) {
            int flat = j * NT + t;
            int m = flat >> 6, cp2 = flat & 63;
            float2 a = *(const float2*)&g_KVp[kvb  + (size_t)m * D + 2 * cp2];
            float2 b = *(const float2*)&g_KVp[kvb2 + (size_t)m * D + 2 * cp2];
            uint32_t hi, lo; split2(a.x + b.x, a.y + b.y, hi, lo);
            uint32_t o = toff(m, 2 * cp2);
            *(uint32_t*)(sm + o)        = hi;
            *(uint32_t*)(sm + TILE + o) = lo;
        }
    }
    // ---- Z denominator per l ----
    if (t < 128) {
        float za = 0.f;
        #pragma unroll 8
        for (int j = 0; j < 64; j++) {
            uint32_t o = toff(t, 2 * j);
            float2 q = unsplit(*(uint32_t*)(sm + 4 * TILE + o), *(uint32_t*)(sm + 5 * TILE + o));
            za += q.x * aux[128 + 2 * j] + q.y * aux[128 + 2 * j + 1];
        }
        aux[256 + t] = 1.f / (za + 1e-6f);
    }
    __syncthreads();

    // ---- out[l][m] = Q x KV^T over d ----
    zero_acc(pr);
    wgemm(pr, su + 4 * TILE, su + 5 * TILE, su, su + TILE, mw, nw, lane);

    // epilogue: apply zinv, write global
    #pragma unroll
    for (int mt = 0; mt < 2; mt++) {
        const int r0 = mw + mt * 16 + (lane >> 2), r1 = r0 + 8;
        const float z0 = aux[256 + r0], z1 = aux[256 + r1];
        const size_t ob0 = ((size_t)(fc * 128 + r0) * NJ + n) * HID + h * D;
        const size_t ob1 = ((size_t)(fc * 128 + r1) * NJ + n) * HID + h * D;
        #pragma unroll
        for (int nt = 0; nt < 4; nt++) {
            const int c = nw + nt * 8 + 2 * (lane & 3);
            *(float2*)&out[ob0 + c] = make_float2(pr[mt][nt][0] * z0, pr[mt][nt][1] * z0);
            *(float2*)&out[ob1 + c] = make_float2(pr[mt][nt][2] * z1, pr[mt][nt][3] * z1);
        }
    }
}

// ===================== launch =====================
extern "C" void kernel_launch(void* const* d_in, const int* in_sizes, int n_in,
                              void* d_out, int out_size) {
    const float* x  = (const float*)d_in[0];
    const float* Wq = (const float*)d_in[1];
    const float* bq = (const float*)d_in[2];
    const float* Wk = (const float*)d_in[3];
    const float* bk = (const float*)d_in[4];
    const float* Wv = (const float*)d_in[5];
    const float* bv = (const float*)d_in[6];
    float* out = (float*)d_out;

    const int smem_sz = 6 * TILE + 1536;   // 198144
    cudaFuncSetAttribute(kv_mma,  cudaFuncAttributeMaxDynamicSharedMemorySize, smem_sz);
    cudaFuncSetAttribute(out_mma, cudaFuncAttributeMaxDynamicSharedMemorySize, smem_sz);

    prep_x<<<dim3(FCH, NJ, 2), 128>>>(x);
    prep_w<<<dim3(3, H, 2), 128>>>(Wq, Wk, Wv);
    kv_mma<<<dim3(NJ, H, PARTS), NT, smem_sz>>>(bk, bv);
    out_mma<<<dim3(F / 128, NJ, H), NT, smem_sz>>>(bq, out);
}

// round 16
// speedup vs baseline: 2.6196x; 1.0298x over previous
#include <cuda_runtime.h>
#include <cuda_bf16.h>
#include <math.h>
#include <stdint.h>

#define F     1024
#define NJ    64
#define C     256
#define HID   1024
#define H     8
#define D     128
#define PARTS 2
#define FCH   8
#define FCPP  (FCH/PARTS)
#define TILE  32768   // [128][128] bf16 swizzled tile
#define NT    512     // threads per MMA block

// Pre-split scratch (~134 MB)
__device__ unsigned char g_xh[FCH][NJ][2][TILE];
__device__ unsigned char g_xl[FCH][NJ][2][TILE];
__device__ unsigned char g_Wth[3][H][2][TILE];
__device__ unsigned char g_Wtl[3][H][2][TILE];
__device__ float g_KVp[(size_t)PARTS*NJ*H*D*D];
__device__ float g_Ksp[(size_t)PARTS*NJ*H*D];

extern __shared__ char smem_raw[];

// ===================== helpers =====================
__device__ __forceinline__ uint32_t smem_u32(const void* p) {
    uint32_t a;
    asm("{ .reg .u64 t; cvta.to.shared.u64 t, %1; cvt.u32.u64 %0, t; }" : "=r"(a) : "l"(p));
    return a;
}
__device__ __forceinline__ float elu1(float v) { return (v >= 0.f) ? (v + 1.f) : __expf(v); }

// SW128 swizzled offset in a [128 r][128 c bf16] tile (c even)
__device__ __forceinline__ uint32_t toff(int r, int c) {
    uint32_t b = (uint32_t)(((r >> 3) + (c >> 6) * 16) * 1024 + (r & 7) * 128 + (c & 63) * 2);
    return b ^ ((b >> 3) & 0x70);
}
__device__ __forceinline__ uint32_t rowbase(int r) { return (uint32_t)((r >> 3) * 1024 + (r & 7) * 128); }
__device__ __forceinline__ uint32_t rowmask(int r) { return (uint32_t)((r & 7) << 4); }
__device__ __forceinline__ uint32_t coladd(uint32_t colx2, uint32_t mask) {
    return ((colx2 & 128u) ? 16384u : 0u) + ((colx2 & 127u) ^ mask);
}

__device__ __forceinline__ void split2(float v0, float v1, uint32_t& hi, uint32_t& lo) {
    __nv_bfloat16 h0 = __float2bfloat16_rn(v0), h1 = __float2bfloat16_rn(v1);
    float r0 = v0 - __bfloat162float(h0), r1 = v1 - __bfloat162float(h1);
    __nv_bfloat16 l0 = __float2bfloat16_rn(r0), l1 = __float2bfloat16_rn(r1);
    unsigned short uh0 = *(unsigned short*)&h0, uh1 = *(unsigned short*)&h1;
    unsigned short ul0 = *(unsigned short*)&l0, ul1 = *(unsigned short*)&l1;
    hi = (uint32_t)uh0 | ((uint32_t)uh1 << 16);
    lo = (uint32_t)ul0 | ((uint32_t)ul1 << 16);
}
__device__ __forceinline__ float2 unsplit(uint32_t hi, uint32_t lo) {
    unsigned short a0 = hi & 0xFFFF, a1 = hi >> 16, b0 = lo & 0xFFFF, b1 = lo >> 16;
    __nv_bfloat16 *p0 = (__nv_bfloat16*)&a0, *p1 = (__nv_bfloat16*)&a1;
    __nv_bfloat16 *q0 = (__nv_bfloat16*)&b0, *q1 = (__nv_bfloat16*)&b1;
    return make_float2(__bfloat162float(*p0) + __bfloat162float(*q0),
                       __bfloat162float(*p1) + __bfloat162float(*q1));
}

__device__ __forceinline__ void ldsm4(uint32_t r[4], uint32_t a) {
    asm volatile("ldmatrix.sync.aligned.m8n8.x4.shared.b16 {%0,%1,%2,%3}, [%4];"
                 : "=r"(r[0]), "=r"(r[1]), "=r"(r[2]), "=r"(r[3]) : "r"(a));
}
__device__ __forceinline__ void mma16816(float d[4], const uint32_t a[4], uint32_t b0, uint32_t b1) {
    asm volatile(
        "mma.sync.aligned.m16n8k16.row.col.f32.bf16.bf16.f32 "
        "{%0,%1,%2,%3}, {%4,%5,%6,%7}, {%8,%9}, {%0,%1,%2,%3};"
        : "+f"(d[0]), "+f"(d[1]), "+f"(d[2]), "+f"(d[3])
        : "r"(a[0]), "r"(a[1]), "r"(a[2]), "r"(a[3]), "r"(b0), "r"(b1));
}

__device__ __forceinline__ void zero_acc(float a[2][4][4]) {
    #pragma unroll
    for (int i = 0; i < 2; i++)
        #pragma unroll
        for (int j = 0; j < 4; j++)
            #pragma unroll
            for (int q = 0; q < 4; q++) a[i][j][q] = 0.f;
}

// cp.async 32KB tile copy, NT threads
__device__ __forceinline__ void cp_tile_async(uint32_t dst, const unsigned char* src, int t) {
    #pragma unroll
    for (int j = 0; j < 4; j++) {
        int idx = (t + j * NT) * 16;
        asm volatile("cp.async.cg.shared.global [%0], [%1], 16;"
                     :: "r"(dst + idx), "l"(src + idx));
    }
}
#define CP_COMMIT() asm volatile("cp.async.commit_group;" ::: "memory")
#define CP_WAIT()   asm volatile("cp.async.wait_group 0;" ::: "memory")

// Warp GEMM: acc (32m x 32n) += A(hi+lo) x B(hi+lo)^T over k=128.
// Combo-reordered: RAW reuse distance 8 independent HMMAs.
__device__ void wgemm(float acc[2][4][4],
                      uint32_t AH, uint32_t AL, uint32_t BH, uint32_t BL,
                      int mw, int nw, int lane)
{
    const int phase = lane >> 3, lr = lane & 7;
    const int arow0 = mw + ((phase & 1) << 3) + lr;
    const uint32_t ab0 = rowbase(arow0), am0 = rowmask(arow0);
    const uint32_t ab1 = rowbase(arow0 + 16), am1 = rowmask(arow0 + 16);
    const int acol = (phase >> 1) << 3;
    const int brow_off = ((phase >> 1) << 3) + lr;
    const int bcol = (phase & 1) << 3;
    uint32_t bb[2], bm[2];
    #pragma unroll
    for (int i = 0; i < 2; i++) {
        int r = nw + i * 16 + brow_off;
        bb[i] = rowbase(r); bm[i] = rowmask(r);
    }

    #pragma unroll
    for (int k = 0; k < 8; k++) {
        uint32_t ah0[4], ah1[4], al0[4], al1[4];
        uint32_t ca = (uint32_t)((k * 16 + acol) * 2);
        uint32_t oA0 = ab0 + coladd(ca, am0);
        uint32_t oA1 = ab1 + coladd(ca, am1);
        ldsm4(ah0, AH + oA0); ldsm4(ah1, AH + oA1);
        ldsm4(al0, AL + oA0); ldsm4(al1, AL + oA1);
        uint32_t bh[2][4], bl[2][4];
        uint32_t cb = (uint32_t)((k * 16 + bcol) * 2);
        #pragma unroll
        for (int i = 0; i < 2; i++) {
            uint32_t o = coladd(cb, bm[i]) + bb[i];
            ldsm4(bh[i], BH + o);
            ldsm4(bl[i], BL + o);
        }
        #pragma unroll
        for (int nt = 0; nt < 4; nt++) {
            uint32_t b0 = bh[nt >> 1][(nt & 1) * 2], b1 = bh[nt >> 1][(nt & 1) * 2 + 1];
            mma16816(acc[0][nt], ah0, b0, b1);
            mma16816(acc[1][nt], ah1, b0, b1);
        }
        #pragma unroll
        for (int nt = 0; nt < 4; nt++) {
            uint32_t b0 = bl[nt >> 1][(nt & 1) * 2], b1 = bl[nt >> 1][(nt & 1) * 2 + 1];
            mma16816(acc[0][nt], ah0, b0, b1);
            mma16816(acc[1][nt], ah1, b0, b1);
        }
        #pragma unroll
        for (int nt = 0; nt < 4; nt++) {
            uint32_t b0 = bh[nt >> 1][(nt & 1) * 2], b1 = bh[nt >> 1][(nt & 1) * 2 + 1];
            mma16816(acc[0][nt], al0, b0, b1);
            mma16816(acc[1][nt], al1, b0, b1);
        }
    }
}

// ===================== prep kernels =====================
__global__ __launch_bounds__(128) void prep_x(const float* __restrict__ x) {
    const int fc = blockIdx.x, n = blockIdx.y, cc = blockIdx.z;
    const int t = threadIdx.x, cp = t & 63, rh = t >> 6;
    unsigned char* dh = &g_xh[fc][n][cc][0];
    unsigned char* dl = &g_xl[fc][n][cc][0];
    for (int jj = 0; jj < 64; jj++) {
        int f = jj * 2 + rh;
        float2 v = *(const float2*)&x[((size_t)(fc * 128 + f) * NJ + n) * C + cc * 128 + 2 * cp];
        uint32_t hi, lo; split2(v.x, v.y, hi, lo);
        uint32_t o = toff(f, 2 * cp);
        *(uint32_t*)(dh + o) = hi;
        *(uint32_t*)(dl + o) = lo;
    }
}
__global__ __launch_bounds__(128) void prep_w(
    const float* __restrict__ Wq, const float* __restrict__ Wk, const float* __restrict__ Wv) {
    const int z = blockIdx.x, h = blockIdx.y, cc = blockIdx.z;
    const float* W = (z == 0) ? Wq : (z == 1) ? Wk : Wv;
    const int t = threadIdx.x, cp = t & 63, rh = t >> 6;
    unsigned char* dh = &g_Wth[z][h][cc][0];
    unsigned char* dl = &g_Wtl[z][h][cc][0];
    for (int jj = 0; jj < 64; jj++) {
        int o = jj * 2 + rh;
        float w0 = W[(size_t)(cc * 128 + 2 * cp) * HID + h * D + o];
        float w1 = W[(size_t)(cc * 128 + 2 * cp + 1) * HID + h * D + o];
        uint32_t hi, lo; split2(w0, w1, hi, lo);
        uint32_t off = toff(o, 2 * cp);
        *(uint32_t*)(dh + off) = hi;
        *(uint32_t*)(dl + off) = lo;
    }
}

// ===================== kernel A: K/V proj + KV accumulation =====================
// grid (NJ, H, PARTS), NT threads, 7 tile slots + aux.
__global__ __launch_bounds__(NT, 1) void kv_mma(
    const float* __restrict__ bk, const float* __restrict__ bv)
{
    const int n = blockIdx.x, h = blockIdx.y, p = blockIdx.z;
    const int t = threadIdx.x, lane = t & 31, w = t >> 5;
    const int mw = (w >> 2) * 32, nw = (w & 3) * 32;
    char* sm = smem_raw;
    const uint32_t su = smem_u32(smem_raw);
    float* aux = (float*)(sm + 7 * TILE);   // [0..127] bk, [128..255] bv, [256..383] ksum partial

    if (t < 128) { aux[t] = bk[h * D + t]; aux[128 + t] = bv[h * D + t]; aux[256 + t] = 0.f; }

    float kvac[2][4][4]; zero_acc(kvac);
    float ksum = 0.f;
    __syncthreads();

    for (int fi = 0; fi < FCPP; fi++) {
        const int fc = p * FCPP + fi;

        // ======== K projection: Kt[d][f] ========
        float pr[2][4][4]; zero_acc(pr);
        // cc0 operands: x->S2/S3, Wk->S4/S5
        cp_tile_async(su + 2 * TILE, &g_xh[fc][n][0][0], t);
        cp_tile_async(su + 3 * TILE, &g_xl[fc][n][0][0], t);
        cp_tile_async(su + 4 * TILE, &g_Wth[1][h][0][0], t);
        cp_tile_async(su + 5 * TILE, &g_Wtl[1][h][0][0], t);
        CP_COMMIT(); CP_WAIT();
        __syncthreads();
        // prefetch cc1: xh1->S6, Wkh1->S0, Wkl1->S1
        cp_tile_async(su + 6 * TILE, &g_xh[fc][n][1][0], t);
        cp_tile_async(su + 0 * TILE, &g_Wth[1][h][1][0], t);
        cp_tile_async(su + 1 * TILE, &g_Wtl[1][h][1][0], t);
        CP_COMMIT();
        wgemm(pr, su + 4 * TILE, su + 5 * TILE, su + 2 * TILE, su + 3 * TILE, mw, nw, lane);
        __syncthreads();
        cp_tile_async(su + 2 * TILE, &g_xl[fc][n][1][0], t);   // xl1->S2
        CP_COMMIT(); CP_WAIT();
        __syncthreads();
        wgemm(pr, su + 0 * TILE, su + 1 * TILE, su + 6 * TILE, su + 2 * TILE, mw, nw, lane);
        __syncthreads();

        // K epilogue -> Kt: hi=S3, lo=S4; ksum partials via smem atomics
        {
            char* Kth = sm + 3 * TILE; char* Ktl = sm + 4 * TILE;
            #pragma unroll
            for (int mt = 0; mt < 2; mt++) {
                const int r0 = mw + mt * 16 + (lane >> 2), r1 = r0 + 8;
                const float bs0 = aux[r0], bs1 = aux[r1];
                float s0 = 0.f, s1 = 0.f;
                #pragma unroll
                for (int nt = 0; nt < 4; nt++) {
                    const int c = nw + nt * 8 + 2 * (lane & 3);
                    float v00 = elu1(pr[mt][nt][0] + bs0), v01 = elu1(pr[mt][nt][1] + bs0);
                    float v10 = elu1(pr[mt][nt][2] + bs1), v11 = elu1(pr[mt][nt][3] + bs1);
                    s0 += v00 + v01; s1 += v10 + v11;
                    uint32_t hi, lo;
                    split2(v00, v01, hi, lo);
                    *(uint32_t*)(Kth + toff(r0, c)) = hi;
                    *(uint32_t*)(Ktl + toff(r0, c)) = lo;
                    split2(v10, v11, hi, lo);
                    *(uint32_t*)(Kth + toff(r1, c)) = hi;
                    *(uint32_t*)(Ktl + toff(r1, c)) = lo;
                }
                s0 += __shfl_xor_sync(0xFFFFFFFFu, s0, 1); s0 += __shfl_xor_sync(0xFFFFFFFFu, s0, 2);
                s1 += __shfl_xor_sync(0xFFFFFFFFu, s1, 1); s1 += __shfl_xor_sync(0xFFFFFFFFu, s1, 2);
                if ((lane & 3) == 0) { atomicAdd(&aux[256 + r0], s0); atomicAdd(&aux[256 + r1], s1); }
            }
        }

        // ======== V projection: Vt[m][f] ========
        zero_acc(pr);
        // cc0 operands: x->S5/S6, Wv->S0/S1
        cp_tile_async(su + 5 * TILE, &g_xh[fc][n][0][0], t);
        cp_tile_async(su + 6 * TILE, &g_xl[fc][n][0][0], t);
        cp_tile_async(su + 0 * TILE, &g_Wth[2][h][0][0], t);
        cp_tile_async(su + 1 * TILE, &g_Wtl[2][h][0][0], t);
        CP_COMMIT(); CP_WAIT();
        __syncthreads();
        cp_tile_async(su + 2 * TILE, &g_xh[fc][n][1][0], t);   // prefetch xh1->S2
        CP_COMMIT();
        wgemm(pr, su + 0 * TILE, su + 1 * TILE, su + 5 * TILE, su + 6 * TILE, mw, nw, lane);
        __syncthreads();
        cp_tile_async(su + 5 * TILE, &g_xl[fc][n][1][0], t);   // xl1->S5
        cp_tile_async(su + 6 * TILE, &g_Wth[2][h][1][0], t);   // Wvh1->S6
        cp_tile_async(su + 0 * TILE, &g_Wtl[2][h][1][0], t);   // Wvl1->S0
        CP_COMMIT(); CP_WAIT();
        __syncthreads();
        wgemm(pr, su + 6 * TILE, su + 0 * TILE, su + 2 * TILE, su + 5 * TILE, mw, nw, lane);
        __syncthreads();

        // V epilogue -> Vt: hi=S1, lo=S5
        {
            char* Vth = sm + 1 * TILE; char* Vtl = sm + 5 * TILE;
            #pragma unroll
            for (int mt = 0; mt < 2; mt++) {
                const int r0 = mw + mt * 16 + (lane >> 2), r1 = r0 + 8;
                const float bs0 = aux[128 + r0], bs1 = aux[128 + r1];
                #pragma unroll
                for (int nt = 0; nt < 4; nt++) {
                    const int c = nw + nt * 8 + 2 * (lane & 3);
                    uint32_t hi, lo;
                    split2(pr[mt][nt][0] + bs0, pr[mt][nt][1] + bs0, hi, lo);
                    *(uint32_t*)(Vth + toff(r0, c)) = hi;
                    *(uint32_t*)(Vtl + toff(r0, c)) = lo;
                    split2(pr[mt][nt][2] + bs1, pr[mt][nt][3] + bs1, hi, lo);
                    *(uint32_t*)(Vth + toff(r1, c)) = hi;
                    *(uint32_t*)(Vtl + toff(r1, c)) = lo;
                }
            }
        }
        if (t < 128) { ksum += aux[256 + t]; aux[256 + t] = 0.f; }
        __syncthreads();   // Vt visible

        // ======== KV[m][d] += Vt x Kt^T over f ========
        wgemm(kvac, su + 1 * TILE, su + 5 * TILE, su + 3 * TILE, su + 4 * TILE, mw, nw, lane);
        __syncthreads();   // all reads done before next fi overwrites
    }

    // write KV partial + Ksum partial
    const int nh = n * H + h;
    const size_t kvb = ((size_t)p * NJ * H + nh) * (size_t)(D * D);
    #pragma unroll
    for (int mt = 0; mt < 2; mt++) {
        const int r0 = mw + mt * 16 + (lane >> 2), r1 = r0 + 8;
        #pragma unroll
        for (int nt = 0; nt < 4; nt++) {
            const int c = nw + nt * 8 + 2 * (lane & 3);
            *(float2*)&g_KVp[kvb + (size_t)r0 * D + c] = make_float2(kvac[mt][nt][0], kvac[mt][nt][1]);
            *(float2*)&g_KVp[kvb + (size_t)r1 * D + c] = make_float2(kvac[mt][nt][2], kvac[mt][nt][3]);
        }
    }
    if (t < 128) g_Ksp[((size_t)p * NJ * H + nh) * D + t] = ksum;
}

// ===================== kernel B: Q proj + output GEMM + Z =====================
// grid (F/128, NJ, H), NT threads, 7 tile slots + aux.
__global__ __launch_bounds__(NT, 1) void out_mma(
    const float* __restrict__ bq, float* __restrict__ out)
{
    const int fc = blockIdx.x, n = blockIdx.y, h = blockIdx.z;
    const int nh = n * H + h;
    const int t = threadIdx.x, lane = t & 31, w = t >> 5;
    const int mw = (w >> 2) * 32, nw = (w & 3) * 32;
    char* sm = smem_raw;
    const uint32_t su = smem_u32(smem_raw);
    float* aux = (float*)(sm + 7 * TILE);   // [0..127] bq, [128..255] ks, [256..383] zpart, [384..511] zinv

    if (t < 128) {
        aux[t] = bq[h * D + t];
        aux[128 + t] = g_Ksp[(size_t)nh * D + t] + g_Ksp[(size_t)NJ * H * D + (size_t)nh * D + t];
        aux[256 + t] = 0.f;
    }

    // ---- Q projection: Q[l][d] = x . Wq^T ----
    float pr[2][4][4]; zero_acc(pr);
    // cc0: x->S0/S1, Wq->S2/S3
    cp_tile_async(su + 0 * TILE, &g_xh[fc][n][0][0], t);
    cp_tile_async(su + 1 * TILE, &g_xl[fc][n][0][0], t);
    cp_tile_async(su + 2 * TILE, &g_Wth[0][h][0][0], t);
    cp_tile_async(su + 3 * TILE, &g_Wtl[0][h][0][0], t);
    CP_COMMIT(); CP_WAIT();
    __syncthreads();
    // prefetch cc1: xh1->S4, xl1->S5, Wqh1->S6
    cp_tile_async(su + 4 * TILE, &g_xh[fc][n][1][0], t);
    cp_tile_async(su + 5 * TILE, &g_xl[fc][n][1][0], t);
    cp_tile_async(su + 6 * TILE, &g_Wth[0][h][1][0], t);
    CP_COMMIT();
    wgemm(pr, su + 0 * TILE, su + 1 * TILE, su + 2 * TILE, su + 3 * TILE, mw, nw, lane);
    __syncthreads();
    cp_tile_async(su + 0 * TILE, &g_Wtl[0][h][1][0], t);   // Wql1->S0
    CP_COMMIT(); CP_WAIT();
    __syncthreads();
    wgemm(pr, su + 4 * TILE, su + 5 * TILE, su + 6 * TILE, su + 0 * TILE, mw, nw, lane);
    __syncthreads();

    // Q epilogue -> Q: hi=S4, lo=S5 (bias by column d)
    {
        char* Qh = sm + 4 * TILE; char* Ql = sm + 5 * TILE;
        #pragma unroll
        for (int mt = 0; mt < 2; mt++) {
            const int r0 = mw + mt * 16 + (lane >> 2), r1 = r0 + 8;
            #pragma unroll
            for (int nt = 0; nt < 4; nt++) {
                const int c = nw + nt * 8 + 2 * (lane & 3);
                const float b0 = aux[c], b1 = aux[c + 1];
                uint32_t hi, lo;
                split2(elu1(pr[mt][nt][0] + b0), elu1(pr[mt][nt][1] + b1), hi, lo);
                *(uint32_t*)(Qh + toff(r0, c)) = hi;
                *(uint32_t*)(Ql + toff(r0, c)) = lo;
                split2(elu1(pr[mt][nt][2] + b0), elu1(pr[mt][nt][3] + b1), hi, lo);
                *(uint32_t*)(Qh + toff(r1, c)) = hi;
                *(uint32_t*)(Ql + toff(r1, c)) = lo;
            }
        }
    }
    // KV load (sum partials) -> hi=S2, lo=S3
    {
        const size_t kvb  = (size_t)nh * (size_t)(D * D);
        const size_t kvb2 = (size_t)NJ * H * D * D + kvb;
        #pragma unroll 4
        for (int j = 0; j < 8192 / NT; j++) {
            int flat = j * NT + t;
            int m = flat >> 6, cp2 = flat & 63;
            float2 a = *(const float2*)&g_KVp[kvb  + (size_t)m * D + 2 * cp2];
            float2 b = *(const float2*)&g_KVp[kvb2 + (size_t)m * D + 2 * cp2];
            uint32_t hi, lo; split2(a.x + b.x, a.y + b.y, hi, lo);
            uint32_t o = toff(m, 2 * cp2);
            *(uint32_t*)(sm + 2 * TILE + o) = hi;
            *(uint32_t*)(sm + 3 * TILE + o) = lo;
        }
    }
    __syncthreads();   // Q + KV visible

    // ---- Z denominator, all 512 threads: thread (l, q) sums a 32-wide d-strip ----
    {
        const int l = t & 127, q = t >> 7;
        float za = 0.f;
        #pragma unroll 4
        for (int j = 0; j < 16; j++) {
            const int dd = q * 32 + 2 * j;
            uint32_t o = toff(l, dd);
            float2 qv = unsplit(*(uint32_t*)(sm + 4 * TILE + o), *(uint32_t*)(sm + 5 * TILE + o));
            za += qv.x * aux[128 + dd] + qv.y * aux[128 + dd + 1];
        }
        atomicAdd(&aux[256 + l], za);
    }
    __syncthreads();
    if (t < 128) aux[384 + t] = 1.f / (aux[256 + t] + 1e-6f);
    __syncthreads();

    // ---- out[l][m] = Q x KV^T over d ----
    zero_acc(pr);
    wgemm(pr, su + 4 * TILE, su + 5 * TILE, su + 2 * TILE, su + 3 * TILE, mw, nw, lane);

    // epilogue: apply zinv, write global
    #pragma unroll
    for (int mt = 0; mt < 2; mt++) {
        const int r0 = mw + mt * 16 + (lane >> 2), r1 = r0 + 8;
        const float z0 = aux[384 + r0], z1 = aux[384 + r1];
        const size_t ob0 = ((size_t)(fc * 128 + r0) * NJ + n) * HID + h * D;
        const size_t ob1 = ((size_t)(fc * 128 + r1) * NJ + n) * HID + h * D;
        #pragma unroll
        for (int nt = 0; nt < 4; nt++) {
            const int c = nw + nt * 8 + 2 * (lane & 3);
            *(float2*)&out[ob0 + c] = make_float2(pr[mt][nt][0] * z0, pr[mt][nt][1] * z0);
            *(float2*)&out[ob1 + c] = make_float2(pr[mt][nt][2] * z1, pr[mt][nt][3] * z1);
        }
    }
}

// ===================== launch =====================
extern "C" void kernel_launch(void* const* d_in, const int* in_sizes, int n_in,
                              void* d_out, int out_size) {
    const float* x  = (const float*)d_in[0];
    const float* Wq = (const float*)d_in[1];
    const float* bq = (const float*)d_in[2];
    const float* Wk = (const float*)d_in[3];
    const float* bk = (const float*)d_in[4];
    const float* Wv = (const float*)d_in[5];
    const float* bv = (const float*)d_in[6];
    float* out = (float*)d_out;

    const int smem_sz = 7 * TILE + 2048;   // 231424 <= 232448
    cudaFuncSetAttribute(kv_mma,  cudaFuncAttributeMaxDynamicSharedMemorySize, smem_sz);
    cudaFuncSetAttribute(out_mma, cudaFuncAttributeMaxDynamicSharedMemorySize, smem_sz);

    prep_x<<<dim3(FCH, NJ, 2), 128>>>(x);
    prep_w<<<dim3(3, H, 2), 128>>>(Wq, Wk, Wv);
    kv_mma<<<dim3(NJ, H, PARTS), NT, smem_sz>>>(bk, bv);
    out_mma<<<dim3(F / 128, NJ, H), NT, smem_sz>>>(bq, out);
}